// round 12
// baseline (speedup 1.0000x reference)
#include <cuda_runtime.h>
#include <cuda_bf16.h>
#include <cuda_fp16.h>
#include <cstdint>

// Problem constants
#define BN 32768
#define DN 256
#define KN 2048

// Output layout (fp32, concatenated in reference return order)
#define Q_OFF    0
#define TAIL_OFF (BN*DN)
#define IND_OFF  (BN*DN + 2)

// Stage-2 shortlist margin (worst-case bf16 path error ~1.4e-3; >=2x safety)
#define MARGIN 4.0e-3f

// Scratch (device globals; no allocation allowed)
__device__ float g_rowA[BN];            // sum(latents^2) per row
__device__ float g_rowB[KN];            // sum(embedding^2) per code
__device__ int   g_minidx[BN];          // exact argmin index per row
__device__ int   g_counts[KN];          // histogram
__device__ float g_sqsum;               // sum (q - l)^2
__device__ float g_mindsum;             // sum of min dists
__device__ __nv_bfloat16 g_latbf[(size_t)BN * DN];  // bf16 latents
__device__ __nv_bfloat16 g_embbf[(size_t)KN * DN];  // bf16 embedding
__device__ __half        g_s[(size_t)BN * KN];      // approx s = B_k - 2*dot (fp16)

// ---------------------------------------------------------------------------
__global__ void vq_init()
{
    int t = blockIdx.x * blockDim.x + threadIdx.x;
    if (t < KN) g_counts[t] = 0;
    if (t == 0) { g_sqsum = 0.f; g_mindsum = 0.f; }
}

// Row sum of squares (reference-shadowing rounding), fused bf16 conversion.
__global__ void vq_rowsumsq(const float* __restrict__ x, int nrows, int which)
{
    int gw   = (blockIdx.x * blockDim.x + threadIdx.x) >> 5;
    int lane = threadIdx.x & 31;
    if (gw >= nrows) return;
    const float* row = x + (size_t)gw * DN;
    float s = 0.f;
    #pragma unroll
    for (int j = 0; j < DN / 32; j++) {
        float v = row[lane + 32 * j];
        s = __fadd_rn(s, __fmul_rn(v, v));
        __nv_bfloat16 bv = __float2bfloat16(v);   // rne
        if (which) g_embbf[(size_t)gw * DN + lane + 32 * j] = bv;
        else       g_latbf[(size_t)gw * DN + lane + 32 * j] = bv;
    }
    #pragma unroll
    for (int off = 16; off > 0; off >>= 1)
        s = __fadd_rn(s, __shfl_down_sync(0xffffffffu, s, off));
    if (lane == 0) {
        if (which) g_rowB[gw] = s; else g_rowA[gw] = s;
    }
}

// ---------------------------------------------------------------------------
// Stage 1: bf16 warp-MMA GEMM (mma.sync m16n8k16), cp.async double-buffered.
// Block = 128 rows x 128 codes; K=256 as 4 chunks of 64, 2-stage pipeline.
// Smem/stage = 32 KB (A 16K + B 16K); 2 stages + b2s = 66 KB -> 2 blocks/SM.
// 8 warps in 2(m) x 4(n); warp tile = 64 x 32.
// Smem rows are 128B (64 bf16), 16B chunks XOR-swizzled (c ^ (r&7)).
// Emits s = B_k - 2*dot (fp16) for every (row, code) pair.
// ---------------------------------------------------------------------------
#define STAGE_BYTES 32768
#define B2_OFF      65536
#define SMEM_TOT    (65536 + 512)

__device__ __forceinline__ void ldsm_x4(uint32_t& r0, uint32_t& r1,
                                        uint32_t& r2, uint32_t& r3, uint32_t addr)
{
    asm volatile("ldmatrix.sync.aligned.m8n8.x4.shared.b16 {%0,%1,%2,%3}, [%4];"
                 : "=r"(r0), "=r"(r1), "=r"(r2), "=r"(r3) : "r"(addr));
}
__device__ __forceinline__ void mma_bf16(float* c, uint32_t a0, uint32_t a1,
                                         uint32_t a2, uint32_t a3,
                                         uint32_t b0, uint32_t b1)
{
    asm volatile(
        "mma.sync.aligned.m16n8k16.row.col.f32.bf16.bf16.f32 "
        "{%0,%1,%2,%3}, {%4,%5,%6,%7}, {%8,%9}, {%0,%1,%2,%3};"
        : "+f"(c[0]), "+f"(c[1]), "+f"(c[2]), "+f"(c[3])
        : "r"(a0), "r"(a1), "r"(a2), "r"(a3), "r"(b0), "r"(b1));
}
__device__ __forceinline__ uint32_t smem_u32(const void* p) {
    uint32_t a;
    asm("{ .reg .u64 t; cvta.to.shared.u64 t, %1; cvt.u32.u64 %0, t; }"
        : "=r"(a) : "l"(p));
    return a;
}
__device__ __forceinline__ void cp_async16(uint32_t dst, const void* src)
{
    asm volatile("cp.async.cg.shared.global [%0], [%1], 16;"
                 :: "r"(dst), "l"(src));
}
#define CP_COMMIT() asm volatile("cp.async.commit_group;" ::: "memory")
#define CP_WAIT(N)  asm volatile("cp.async.wait_group %0;" :: "n"(N) : "memory")

__global__ __launch_bounds__(256, 2) void vq_gemm()
{
    extern __shared__ char smem[];
    uint32_t smem_base = smem_u32(smem);
    float* b2s = (float*)(smem + B2_OFF);

    int tid  = threadIdx.x;
    int wid  = tid >> 5;
    int lane = tid & 31;
    int gid  = lane >> 2;       // mma group id (row within 8)
    int tig  = lane & 3;        // thread-in-group (col pair)
    int wm   = wid >> 2;        // 0..1
    int wn   = wid & 3;         // 0..3

    int row0 = (blockIdx.x >> 4) * 128;
    int kc0  = (blockIdx.x & 15) * 128;

    if (tid < 128) b2s[tid] = g_rowB[kc0 + tid];

    // Per-thread load slice: 4 chunks of 16B for A, 4 for B per stage
    int lr = tid >> 1;                 // 0..127 (two threads per row)
    int lc0 = (tid & 1) * 4;           // chunk 0..3 or 4..7

    auto issue_chunk = [&](int kd, int stage) {
        uint32_t sa = smem_base + stage * STAGE_BYTES;
        const __nv_bfloat16* ga = g_latbf + (size_t)(row0 + lr) * DN + kd * 64;
        const __nv_bfloat16* gb = g_embbf + (size_t)(kc0  + lr) * DN + kd * 64;
        #pragma unroll
        for (int c = lc0; c < lc0 + 4; c++) {
            cp_async16(sa + lr * 128 + ((c ^ (lr & 7)) << 4), ga + c * 8);
        }
        #pragma unroll
        for (int c = lc0; c < lc0 + 4; c++) {
            cp_async16(sa + 16384 + lr * 128 + ((c ^ (lr & 7)) << 4), gb + c * 8);
        }
        CP_COMMIT();
    };

    float acc[4][4][4];
    #pragma unroll
    for (int mt = 0; mt < 4; mt++)
        #pragma unroll
        for (int nt = 0; nt < 4; nt++)
            #pragma unroll
            for (int q = 0; q < 4; q++) acc[mt][nt][q] = 0.f;

    int j   = lane >> 3;        // ldmatrix address group 0..3
    int rin = lane & 7;

    issue_chunk(0, 0);          // prologue

    for (int kd = 0; kd < 4; kd++) {
        if (kd + 1 < 4) issue_chunk(kd + 1, (kd + 1) & 1);
        if (kd + 1 < 4) { CP_WAIT(1); } else { CP_WAIT(0); }
        __syncthreads();

        uint32_t sa = smem_base + (kd & 1) * STAGE_BYTES;
        uint32_t sb = sa + 16384;

        #pragma unroll
        for (int kt = 0; kt < 4; kt++) {
            // A fragments: 4 m-tiles via ldsm_x4
            uint32_t af[4][4];
            #pragma unroll
            for (int mt = 0; mt < 4; mt++) {
                int row = wm * 64 + mt * 16 + (j & 1) * 8 + rin;
                int ch  = 2 * kt + (j >> 1);
                ldsm_x4(af[mt][0], af[mt][1], af[mt][2], af[mt][3],
                        sa + row * 128 + ((ch ^ (row & 7)) << 4));
            }
            // B fragments: 2 n-tile PAIRS via ldsm_x4 (r0,r1 = even nt; r2,r3 = odd nt)
            uint32_t bf[4][2];
            #pragma unroll
            for (int np = 0; np < 2; np++) {
                int code = wn * 32 + np * 16 + (j >> 1) * 8 + rin;
                int ch   = 2 * kt + (j & 1);
                ldsm_x4(bf[np * 2][0], bf[np * 2][1], bf[np * 2 + 1][0], bf[np * 2 + 1][1],
                        sb + code * 128 + ((ch ^ (code & 7)) << 4));
            }
            #pragma unroll
            for (int mt = 0; mt < 4; mt++)
                #pragma unroll
                for (int nt = 0; nt < 4; nt++)
                    mma_bf16(acc[mt][nt], af[mt][0], af[mt][1], af[mt][2], af[mt][3],
                             bf[nt][0], bf[nt][1]);
        }
        __syncthreads();        // stage consumed before next-next issue overwrites
    }

    // Epilogue: s = B2[code] - 2*acc, store fp16
    #pragma unroll
    for (int mt = 0; mt < 4; mt++) {
        int r0 = wm * 64 + mt * 16 + gid;
        #pragma unroll
        for (int nt = 0; nt < 4; nt++) {
            int c0 = wn * 32 + nt * 8 + tig * 2;
            float b20 = b2s[c0], b21 = b2s[c0 + 1];
            float s00 = b20 - 2.0f * acc[mt][nt][0];
            float s01 = b21 - 2.0f * acc[mt][nt][1];
            float s10 = b20 - 2.0f * acc[mt][nt][2];
            float s11 = b21 - 2.0f * acc[mt][nt][3];
            *reinterpret_cast<__half2*>(g_s + (size_t)(row0 + r0) * KN + kc0 + c0)
                = __floats2half2_rn(s00, s01);
            *reinterpret_cast<__half2*>(g_s + (size_t)(row0 + r0 + 8) * KN + kc0 + c0)
                = __floats2half2_rn(s10, s11);
        }
    }
}

// ---------------------------------------------------------------------------
// Stage 2: exact re-check + (merged) histogram/index output/mindsum.
// One warp per row; row's 2048 fp16 s staged in smem. Pass 1: min.
// Pass 2: ballot-compacted candidates, warp-cooperative exact fp32 dot.
// Argmin w/ lowest-index tie-break.
// ---------------------------------------------------------------------------
__global__ __launch_bounds__(256) void vq_select(const float* __restrict__ lat,
                                                 const float* __restrict__ emb,
                                                 float* __restrict__ out_inds)
{
    __shared__ __half srow_s[8][KN];    // 32 KB
    __shared__ float  bsum[8];

    int wip  = threadIdx.x >> 5;        // warp in block
    int lane = threadIdx.x & 31;
    int gw   = blockIdx.x * 8 + wip;    // row

    // Stage row into smem (coalesced uint4)
    const __half* srow = g_s + (size_t)gw * KN;
    #pragma unroll
    for (int q = 0; q < 8; q++) {
        *reinterpret_cast<uint4*>(&srow_s[wip][q * 256 + lane * 8]) =
            *reinterpret_cast<const uint4*>(srow + q * 256 + lane * 8);
    }
    __syncwarp();

    // Preload this row's latents (lane-strided) + A
    float lrow[8];
    #pragma unroll
    for (int u = 0; u < 8; u++) lrow[u] = lat[(size_t)gw * DN + lane + 32 * u];
    float A = g_rowA[gw];

    // Pass 1: min of s (half2 tree)
    const __half2* s2 = reinterpret_cast<const __half2*>(srow_s[wip]);
    __half2 m2 = s2[lane];
    #pragma unroll
    for (int c = 1; c < 32; c++) m2 = __hmin2(m2, s2[c * 32 + lane]);
    float mn = fminf(__low2float(m2), __high2float(m2));
    #pragma unroll
    for (int off = 16; off > 0; off >>= 1)
        mn = fminf(mn, __shfl_xor_sync(0xffffffffu, mn, off));
    float thr = mn + MARGIN;

    // Pass 2: candidates via ballot; cooperative exact recheck
    float bestd = __int_as_float(0x7f800000);
    int   bestk = 0x7fffffff;

    for (int c = 0; c < 32; c++) {
        __half2 h = s2[c * 32 + lane];
        float f0 = __low2float(h), f1 = __high2float(h);
        unsigned mask = __ballot_sync(0xffffffffu, (f0 <= thr) || (f1 <= thr));
        while (mask) {
            int src = __ffs(mask) - 1;
            mask &= mask - 1;
            __half2 hb = s2[c * 32 + src];     // broadcast read
            float fb0 = __low2float(hb), fb1 = __high2float(hb);
            #pragma unroll
            for (int e = 0; e < 2; e++) {
                float fb = e ? fb1 : fb0;
                if (fb <= thr) {
                    int k = (c * 32 + src) * 2 + e;
                    const float* erow = emb + (size_t)k * DN;
                    float acc = 0.f;
                    #pragma unroll
                    for (int u = 0; u < 8; u++)
                        acc = __fmaf_rn(lrow[u], erow[lane + 32 * u], acc);
                    #pragma unroll
                    for (int off = 16; off > 0; off >>= 1)
                        acc = __fadd_rn(acc, __shfl_xor_sync(0xffffffffu, acc, off));
                    float d = __fsub_rn(__fadd_rn(A, g_rowB[k]), __fmul_rn(2.0f, acc));
                    if (d < bestd || (d == bestd && k < bestk)) { bestd = d; bestk = k; }
                }
            }
        }
    }
    if (lane == 0) {
        g_minidx[gw] = bestk;
        out_inds[gw] = (float)bestk;
        atomicAdd(&g_counts[bestk], 1);
        bsum[wip] = bestd;
    }
    __syncthreads();
    if (threadIdx.x == 0) {
        float s = 0.f;
        #pragma unroll
        for (int w = 0; w < 8; w++) s += bsum[w];
        atomicAdd(&g_mindsum, s);
    }
}

// ---------------------------------------------------------------------------
// Gather + straight-through output + squared-error sum.
__global__ void vq_gather(const float* __restrict__ lat, const float* __restrict__ emb,
                          float* __restrict__ outq)
{
    __shared__ float s[256];
    int i4 = blockIdx.x * blockDim.x + threadIdx.x;
    float ls = 0.f;
    if (i4 < BN * DN / 4) {
        int b   = i4 >> 6;
        int idx = g_minidx[b];
        float4 l = reinterpret_cast<const float4*>(lat)[i4];
        float4 q = reinterpret_cast<const float4*>(emb)[(size_t)idx * (DN / 4) + (i4 & 63)];
        float4 o; float d;
        d = __fsub_rn(q.x, l.x); o.x = __fadd_rn(l.x, d); ls = __fmaf_rn(d, d, ls);
        d = __fsub_rn(q.y, l.y); o.y = __fadd_rn(l.y, d); ls = __fmaf_rn(d, d, ls);
        d = __fsub_rn(q.z, l.z); o.z = __fadd_rn(l.z, d); ls = __fmaf_rn(d, d, ls);
        d = __fsub_rn(q.w, l.w); o.w = __fadd_rn(l.w, d); ls = __fmaf_rn(d, d, ls);
        reinterpret_cast<float4*>(outq)[i4] = o;
    }
    s[threadIdx.x] = ls;
    __syncthreads();
    for (int o2 = 128; o2 > 0; o2 >>= 1) {
        if (threadIdx.x < o2) s[threadIdx.x] += s[threadIdx.x + o2];
        __syncthreads();
    }
    if (threadIdx.x == 0) atomicAdd(&g_sqsum, s[0]);
}

__global__ void vq_finalize(float* __restrict__ out_tail)
{
    __shared__ float s[256];
    float loc = 0.f;
    for (int k = threadIdx.x; k < KN; k += 256) {
        float p = (float)g_counts[k] * (1.0f / BN);
        loc += p * logf(p + 1e-10f);
    }
    s[threadIdx.x] = loc;
    __syncthreads();
    for (int o = 128; o > 0; o >>= 1) {
        if (threadIdx.x < o) s[threadIdx.x] += s[threadIdx.x + o];
        __syncthreads();
    }
    if (threadIdx.x == 0) {
        float mse = g_sqsum * (1.0f / (float)(BN * (size_t)DN));
        out_tail[0] = __fadd_rn(__fmul_rn(mse, 0.25f), mse);
        out_tail[1] = -s[0];
        out_tail[2 + BN] = g_mindsum * (1.0f / BN);
    }
}

// ---------------------------------------------------------------------------
extern "C" void kernel_launch(void* const* d_in, const int* in_sizes, int n_in,
                              void* d_out, int out_size)
{
    (void)in_sizes; (void)n_in; (void)out_size;
    const float* lat = (const float*)d_in[0];   // [BN, DN] fp32
    const float* emb = (const float*)d_in[1];   // [KN, DN] fp32
    float* out = (float*)d_out;

    cudaFuncSetAttribute(vq_gemm,
                         cudaFuncAttributeMaxDynamicSharedMemorySize, SMEM_TOT);

    vq_init<<<(KN + 255) / 256, 256>>>();
    vq_rowsumsq<<<(BN * 32) / 256, 256>>>(lat, BN, 0);
    vq_rowsumsq<<<(KN * 32) / 256, 256>>>(emb, KN, 1);
    vq_gemm<<<(BN / 128) * (KN / 128), 256, SMEM_TOT>>>();
    vq_select<<<BN / 8, 256>>>(lat, emb, out + IND_OFF);
    vq_gather<<<(BN * DN / 4) / 256, 256>>>(lat, emb, out + Q_OFF);
    vq_finalize<<<1, 256>>>(out + TAIL_OFF);
}